// round 1
// baseline (speedup 1.0000x reference)
#include <cuda_runtime.h>
#include <math.h>

#define NK      10000
#define SEQ     512
#define KSMAX   11
#define SH_LEN  2048     // covers max padded index ~1871 (PAD_MAX<=510, pad<=510, +511, +(11-ks)*dil<=340)
#define NBINS   96       // dil in [1,85]
#define TPB     256

__device__ int g_padmax;
__device__ int g_hist[NBINS];
__device__ int g_off[NBINS];
__device__ int g_perm[NK];

// --- prep1: padmax = max(base); zero histogram. single block. ---
__global__ void prep1_kernel(const int* __restrict__ base) {
    __shared__ int smax[TPB];
    int tid = threadIdx.x;
    int m = 0;
    for (int i = tid; i < NK; i += TPB) m = max(m, base[i]);
    smax[tid] = m;
    __syncthreads();
    for (int s = TPB / 2; s > 0; s >>= 1) {
        if (tid < s) smax[tid] = max(smax[tid], smax[tid + s]);
        __syncthreads();
    }
    if (tid == 0) g_padmax = smax[0];
    if (tid < NBINS) g_hist[tid] = 0;
}

// --- prep2: histogram of dil ---
__global__ void prep2_kernel(const int* __restrict__ dil) {
    int i = blockIdx.x * blockDim.x + threadIdx.x;
    if (i < NK) {
        int d = dil[i];
        if (d < 0) d = 0;
        if (d >= NBINS) d = NBINS - 1;
        atomicAdd(&g_hist[d], 1);
    }
}

// --- prep3: exclusive prefix over 96 bins (1 thread, trivial) ---
__global__ void prep3_kernel() {
    if (threadIdx.x == 0 && blockIdx.x == 0) {
        int s = 0;
        for (int d = 0; d < NBINS; d++) { g_off[d] = s; s += g_hist[d]; }
    }
}

// --- prep4: scatter into perm, sorted by dil ---
__global__ void prep4_kernel(const int* __restrict__ dil) {
    int i = blockIdx.x * blockDim.x + threadIdx.x;
    if (i < NK) {
        int d = dil[i];
        if (d < 0) d = 0;
        if (d >= NBINS) d = NBINS - 1;
        int pos = atomicAdd(&g_off[d], 1);
        g_perm[pos] = i;
    }
}

// --- main kernel: one thread = one (batch, kernel) pair ---
// Phase decomposition: for phase r (t = q*dil + r), the 11 taps slide by one
// element over the dil-strided subsequence -> ring of 11 register values,
// exactly ONE shared load per produced output.
__global__ __launch_bounds__(TPB) void rocket_main_kernel(
    const float* __restrict__ x,
    const float* __restrict__ W,
    const float* __restrict__ Bias,
    const int*   __restrict__ base,
    const int*   __restrict__ dil,
    const int*   __restrict__ lo,
    float*       __restrict__ out)
{
    __shared__ float sh[SH_LEN];
    const int b   = blockIdx.y;
    const int tid = threadIdx.x;
    const int padmax = g_padmax;

    // zero the padded buffer, then place x at [padmax, padmax+512)
    for (int i = tid; i < SH_LEN; i += TPB) sh[i] = 0.0f;
    __syncthreads();
    for (int i = tid; i < SEQ; i += TPB) sh[padmax + i] = x[b * SEQ + i];
    __syncthreads();

    int slot = blockIdx.x * TPB + tid;
    if (slot >= NK) return;
    const int k = g_perm[slot];

    float w[KSMAX];
#pragma unroll
    for (int j = 0; j < KSMAX; j++) w[j] = W[k * KSMAX + j];
    const float bias = Bias[k];
    const int bs = base[k];
    const int d  = dil[k];
    const int L  = lo[k];

    float maxv = -INFINITY;
    int   cnt  = 0;

    const int rmax = min(d, L);
    for (int r = 0; r < rmax; r++) {
        const int nq = (L - 1 - r) / d + 1;   // >= 1 since r <= L-1
        const float* p = sh + bs + r;
        // warmup: first 10 strided samples into registers
        float y0 = p[0];
        float y1 = p[d];
        float y2 = p[2 * d];
        float y3 = p[3 * d];
        float y4 = p[4 * d];
        float y5 = p[5 * d];
        float y6 = p[6 * d];
        float y7 = p[7 * d];
        float y8 = p[8 * d];
        float y9 = p[9 * d];
        const float* ptr = p + 10 * d;
        for (int q = 0; q < nq; q++) {
            float yA = *ptr;
            ptr += d;
            float acc = w[0] * y0;
            acc = fmaf(w[1],  y1, acc);
            acc = fmaf(w[2],  y2, acc);
            acc = fmaf(w[3],  y3, acc);
            acc = fmaf(w[4],  y4, acc);
            acc = fmaf(w[5],  y5, acc);
            acc = fmaf(w[6],  y6, acc);
            acc = fmaf(w[7],  y7, acc);
            acc = fmaf(w[8],  y8, acc);
            acc = fmaf(w[9],  y9, acc);
            acc = fmaf(w[10], yA, acc);
            acc += bias;
            maxv = fmaxf(maxv, acc);
            cnt += (acc > 0.0f) ? 1 : 0;
            y0 = y1; y1 = y2; y2 = y3; y3 = y4; y4 = y5;
            y5 = y6; y6 = y7; y7 = y8; y8 = y9; y9 = yA;
        }
    }

    const float ppv = (float)cnt / (float)L;
    float* o = out + (size_t)b * (2 * NK) + 2 * k;
    o[0] = maxv;
    o[1] = ppv;
}

extern "C" void kernel_launch(void* const* d_in, const int* in_sizes, int n_in,
                              void* d_out, int out_size) {
    const float* x    = (const float*)d_in[0];
    const float* Wt   = (const float*)d_in[1];
    const float* Bias = (const float*)d_in[2];
    const int*   base = (const int*)d_in[3];
    const int*   dil  = (const int*)d_in[4];
    const int*   lo   = (const int*)d_in[5];
    float* out = (float*)d_out;

    const int nblk = (NK + TPB - 1) / TPB;

    prep1_kernel<<<1, TPB>>>(base);
    prep2_kernel<<<nblk, TPB>>>(dil);
    prep3_kernel<<<1, 32>>>();
    prep4_kernel<<<nblk, TPB>>>(dil);

    dim3 grid(nblk, 8);
    rocket_main_kernel<<<grid, TPB>>>(x, Wt, Bias, base, dil, lo, out);
}

// round 2
// speedup vs baseline: 1.0914x; 1.0914x over previous
#include <cuda_runtime.h>
#include <math.h>

#define NK      10000
#define SEQ     512
#define KSMAX   11
#define SH_LEN  2048     // max padded index ~1871 (padmax<=510, pad<=510, +511, +(11-ks)*d<=340)
#define TPB     128
#define PREP_T  1024
#define PBINS   6144     // key = clamp(d,0,95)*64 + min(L>>4,63)

__device__ int g_padmax;
__device__ int g_perm[NK];

__device__ __forceinline__ int sort_key(int d, int L) {
    if (d < 0) d = 0;
    if (d > 95) d = 95;
    int lb = L >> 4;
    if (lb < 0) lb = 0;
    if (lb > 63) lb = 63;
    return d * 64 + lb;
}

// ---- single fused prep kernel: padmax + counting sort by (dil, lo-bucket) ----
__global__ __launch_bounds__(PREP_T) void prep_fused_kernel(
    const int* __restrict__ base,
    const int* __restrict__ dil,
    const int* __restrict__ lo)
{
    __shared__ int sbins[PBINS];        // 24KB
    __shared__ int spart[PREP_T];       // 4KB
    const int tid = threadIdx.x;

    // --- padmax = max(base) ---
    int m = 0;
    for (int i = tid; i < NK; i += PREP_T) m = max(m, base[i]);
#pragma unroll
    for (int o = 16; o > 0; o >>= 1) m = max(m, __shfl_xor_sync(0xffffffffu, m, o));
    if ((tid & 31) == 0) spart[tid >> 5] = m;
    __syncthreads();
    if (tid == 0) {
        int mm = 0;
        for (int w = 0; w < PREP_T / 32; w++) mm = max(mm, spart[w]);
        g_padmax = mm;
    }

    // --- zero bins ---
    for (int i = tid; i < PBINS; i += PREP_T) sbins[i] = 0;
    __syncthreads();

    // --- histogram ---
    for (int i = tid; i < NK; i += PREP_T)
        atomicAdd(&sbins[sort_key(dil[i], lo[i])], 1);
    __syncthreads();

    // --- exclusive scan over 6144 bins (6 bins per thread + block scan) ---
    int s = 0;
#pragma unroll
    for (int j = 0; j < 6; j++) s += sbins[tid * 6 + j];
    spart[tid] = s;
    __syncthreads();
    for (int off = 1; off < PREP_T; off <<= 1) {
        int v = spart[tid];
        int u = (tid >= off) ? spart[tid - off] : 0;
        __syncthreads();
        spart[tid] = v + u;
        __syncthreads();
    }
    int run = (tid > 0) ? spart[tid - 1] : 0;
#pragma unroll
    for (int j = 0; j < 6; j++) {
        int c = sbins[tid * 6 + j];
        sbins[tid * 6 + j] = run;
        run += c;
    }
    __syncthreads();

    // --- scatter (grouping only; order within identical key irrelevant) ---
    for (int i = tid; i < NK; i += PREP_T) {
        int pos = atomicAdd(&sbins[sort_key(dil[i], lo[i])], 1);
        g_perm[pos] = i;
    }
}

// ---- main kernel: one thread = one (batch, kernel) pair ----
// Phase decomposition + ring of 11 register samples, q-loop unrolled by 11
// with compile-time rotation -> zero shift-MOVs, 1 LDS per output.
__global__ __launch_bounds__(TPB) void rocket_main_kernel(
    const float* __restrict__ x,
    const float* __restrict__ W,
    const float* __restrict__ Bias,
    const int*   __restrict__ base,
    const int*   __restrict__ dil,
    const int*   __restrict__ lo,
    float*       __restrict__ out)
{
    __shared__ float sh[SH_LEN];
    const int b   = blockIdx.y;
    const int tid = threadIdx.x;
    const int padmax = g_padmax;

    for (int i = tid; i < SH_LEN; i += TPB) sh[i] = 0.0f;
    __syncthreads();
    for (int i = tid; i < SEQ; i += TPB) sh[padmax + i] = x[b * SEQ + i];
    __syncthreads();

    const int slot = blockIdx.x * TPB + tid;
    if (slot >= NK) return;
    const int k = g_perm[slot];

    float w[KSMAX];
#pragma unroll
    for (int j = 0; j < KSMAX; j++) w[j] = W[k * KSMAX + j];
    const float bias = Bias[k];
    const int bs = base[k];
    const int d  = dil[k];
    const int L  = lo[k];

    float maxv = -INFINITY;
    int   cnt  = 0;

    const int rmax = min(d, L);
    for (int r = 0; r < rmax; r++) {
        const int nq = (L - 1 - r) / d + 1;   // >= 1
        const float* p = sh + bs + r;

        float y[KSMAX];
#pragma unroll
        for (int j = 0; j < 10; j++) y[j] = p[j * d];
        const float* ptr = p + 10 * d;

        int q = 0;
        for (; q + KSMAX <= nq; q += KSMAX) {
#pragma unroll
            for (int u = 0; u < KSMAX; u++) {
                y[(10 + u) % KSMAX] = *ptr; ptr += d;
                float acc = bias;
#pragma unroll
                for (int j = 0; j < KSMAX; j++)
                    acc = fmaf(w[j], y[(u + j) % KSMAX], acc);
                maxv = fmaxf(maxv, acc);
                cnt += (acc > 0.0f) ? 1 : 0;
            }
        }
#pragma unroll
        for (int u = 0; u < KSMAX; u++) {
            if (q + u < nq) {
                y[(10 + u) % KSMAX] = *ptr; ptr += d;
                float acc = bias;
#pragma unroll
                for (int j = 0; j < KSMAX; j++)
                    acc = fmaf(w[j], y[(u + j) % KSMAX], acc);
                maxv = fmaxf(maxv, acc);
                cnt += (acc > 0.0f) ? 1 : 0;
            }
        }
    }

    const float ppv = (float)cnt / (float)L;
    float* o = out + (size_t)b * (2 * NK) + 2 * k;
    o[0] = maxv;
    o[1] = ppv;
}

extern "C" void kernel_launch(void* const* d_in, const int* in_sizes, int n_in,
                              void* d_out, int out_size) {
    const float* x    = (const float*)d_in[0];
    const float* Wt   = (const float*)d_in[1];
    const float* Bias = (const float*)d_in[2];
    const int*   base = (const int*)d_in[3];
    const int*   dil  = (const int*)d_in[4];
    const int*   lo   = (const int*)d_in[5];
    float* out = (float*)d_out;

    prep_fused_kernel<<<1, PREP_T>>>(base, dil, lo);

    const int nblk = (NK + TPB - 1) / TPB;
    dim3 grid(nblk, 8);
    rocket_main_kernel<<<grid, TPB>>>(x, Wt, Bias, base, dil, lo, out);
}

// round 3
// speedup vs baseline: 1.1272x; 1.0328x over previous
#include <cuda_runtime.h>
#include <math.h>

#define NK      10000
#define SEQ     512
#define KSMAX   11
#define SH_LEN  4096     // padded-phase loads bounded by ~3300; zeros beyond valid region
#define TPB     128
#define PREP_T  1024
#define PBINS   6144     // key = clamp(d,0,95)*64 + min(L>>4,63)

__device__ int g_padmax;
__device__ int g_perm[NK];

__device__ __forceinline__ int sort_key(int d, int L) {
    if (d < 0) d = 0;
    if (d > 95) d = 95;
    int lb = L >> 4;
    if (lb < 0) lb = 0;
    if (lb > 63) lb = 63;
    return d * 64 + lb;
}

// ---- single fused prep kernel: padmax + counting sort by (dil, lo-bucket) ----
__global__ __launch_bounds__(PREP_T) void prep_fused_kernel(
    const int* __restrict__ base,
    const int* __restrict__ dil,
    const int* __restrict__ lo)
{
    __shared__ int sbins[PBINS];
    __shared__ int spart[PREP_T];
    const int tid = threadIdx.x;

    int m = 0;
    for (int i = tid; i < NK; i += PREP_T) m = max(m, base[i]);
#pragma unroll
    for (int o = 16; o > 0; o >>= 1) m = max(m, __shfl_xor_sync(0xffffffffu, m, o));
    if ((tid & 31) == 0) spart[tid >> 5] = m;
    __syncthreads();
    if (tid == 0) {
        int mm = 0;
        for (int w = 0; w < PREP_T / 32; w++) mm = max(mm, spart[w]);
        g_padmax = mm;
    }

    for (int i = tid; i < PBINS; i += PREP_T) sbins[i] = 0;
    __syncthreads();

    for (int i = tid; i < NK; i += PREP_T)
        atomicAdd(&sbins[sort_key(dil[i], lo[i])], 1);
    __syncthreads();

    int s = 0;
#pragma unroll
    for (int j = 0; j < 6; j++) s += sbins[tid * 6 + j];
    spart[tid] = s;
    __syncthreads();
    for (int off = 1; off < PREP_T; off <<= 1) {
        int v = spart[tid];
        int u = (tid >= off) ? spart[tid - off] : 0;
        __syncthreads();
        spart[tid] = v + u;
        __syncthreads();
    }
    int run = (tid > 0) ? spart[tid - 1] : 0;
#pragma unroll
    for (int j = 0; j < 6; j++) {
        int c = sbins[tid * 6 + j];
        sbins[tid * 6 + j] = run;
        run += c;
    }
    __syncthreads();

    for (int i = tid; i < NK; i += PREP_T) {
        int pos = atomicAdd(&sbins[sort_key(dil[i], lo[i])], 1);
        g_perm[pos] = i;
    }
}

// ---- main kernel: one thread = (batch-pair, kernel). float2 shared layout
// interleaves two batches -> 1 LDS.64 feeds 22 FMAs. Phase ring of 11
// float2 samples, q-loop padded to multiples of 11 with predicated
// max/cnt (no branchy tail). One int-div per thread.
__global__ __launch_bounds__(TPB) void rocket_main_kernel(
    const float* __restrict__ x,
    const float* __restrict__ W,
    const float* __restrict__ Bias,
    const int*   __restrict__ base,
    const int*   __restrict__ dil,
    const int*   __restrict__ lo,
    float*       __restrict__ out)
{
    __shared__ float2 sh[SH_LEN];   // 32KB
    const int bp  = blockIdx.y;      // batch pair 0..3
    const int b0  = 2 * bp;
    const int tid = threadIdx.x;
    const int padmax = g_padmax;

    for (int i = tid; i < SH_LEN; i += TPB) sh[i] = make_float2(0.0f, 0.0f);
    __syncthreads();
    for (int i = tid; i < SEQ; i += TPB)
        sh[padmax + i] = make_float2(x[b0 * SEQ + i], x[(b0 + 1) * SEQ + i]);
    __syncthreads();

    const int idx = blockIdx.x * TPB + tid;
    if (idx >= NK) return;
    const int slot = NK - 1 - idx;          // reversed: largest-d blocks first
    const int k = g_perm[slot];

    float w[KSMAX];
#pragma unroll
    for (int j = 0; j < KSMAX; j++) w[j] = W[k * KSMAX + j];
    const float bias = Bias[k];
    const int bs = base[k];
    const int d  = dil[k];
    const int L  = lo[k];

    float max0 = -INFINITY, max1 = -INFINITY;
    int   cnt0 = 0, cnt1 = 0;

    const int q0  = (L - 1) / d;     // single integer division
    const int rem = (L - 1) - q0 * d;
    const int rmax = min(d, L);

    for (int r = 0; r < rmax; r++) {
        const int nq = (r <= rem) ? (q0 + 1) : q0;
        const float2* p = sh + bs + r;

        float2 y[KSMAX];
#pragma unroll
        for (int j = 0; j < 10; j++) y[j] = p[j * d];
        const float2* ptr = p + 10 * d;

        const int nchunk = (nq + 10) / 11;   // div by const -> mul/shift
        for (int c = 0, qbase = 0; c < nchunk; c++, qbase += 11) {
#pragma unroll
            for (int u = 0; u < KSMAX; u++) {
                float2 yA = *ptr; ptr += d;
                y[(10 + u) % KSMAX] = yA;
                float a0 = bias, a1 = bias;
#pragma unroll
                for (int j = 0; j < KSMAX; j++) {
                    const float2 yy = y[(u + j) % KSMAX];
                    a0 = fmaf(w[j], yy.x, a0);
                    a1 = fmaf(w[j], yy.y, a1);
                }
                const bool valid = (qbase + u) < nq;
                max0 = (valid && a0 > max0) ? a0 : max0;
                max1 = (valid && a1 > max1) ? a1 : max1;
                cnt0 += (valid && a0 > 0.0f) ? 1 : 0;
                cnt1 += (valid && a1 > 0.0f) ? 1 : 0;
            }
        }
    }

    const float invL = 1.0f / (float)L;
    float2* o0 = (float2*)(out + (size_t)b0 * (2 * NK) + 2 * k);
    float2* o1 = (float2*)(out + (size_t)(b0 + 1) * (2 * NK) + 2 * k);
    *o0 = make_float2(max0, (float)cnt0 * invL);
    *o1 = make_float2(max1, (float)cnt1 * invL);
}

extern "C" void kernel_launch(void* const* d_in, const int* in_sizes, int n_in,
                              void* d_out, int out_size) {
    const float* x    = (const float*)d_in[0];
    const float* Wt   = (const float*)d_in[1];
    const float* Bias = (const float*)d_in[2];
    const int*   base = (const int*)d_in[3];
    const int*   dil  = (const int*)d_in[4];
    const int*   lo   = (const int*)d_in[5];
    float* out = (float*)d_out;

    prep_fused_kernel<<<1, PREP_T>>>(base, dil, lo);

    const int nblk = (NK + TPB - 1) / TPB;
    dim3 grid(nblk, 4);
    rocket_main_kernel<<<grid, TPB>>>(x, Wt, Bias, base, dil, lo, out);
}

// round 4
// speedup vs baseline: 1.1666x; 1.0349x over previous
#include <cuda_runtime.h>
#include <math.h>

#define NK      10000
#define SEQ     512
#define KSMAX   11
#define SH_LEN  4096     // max (padded) read index ~3320
#define TPB     64
#define PREP_T  1024
#define PBINS   6144     // key = clamp(d,0,95)*64 + min(L>>4,63)

__device__ int g_padmax;
__device__ int g_perm[NK];

__device__ __forceinline__ int sort_key(int d, int L) {
    if (d < 0) d = 0;
    if (d > 95) d = 95;
    int lb = L >> 4;
    if (lb < 0) lb = 0;
    if (lb > 63) lb = 63;
    return d * 64 + lb;
}

// ---- single fused prep kernel: padmax + counting sort by (dil, lo-bucket) ----
__global__ __launch_bounds__(PREP_T) void prep_fused_kernel(
    const int* __restrict__ base,
    const int* __restrict__ dil,
    const int* __restrict__ lo)
{
    __shared__ int sbins[PBINS];
    __shared__ int spart[PREP_T];
    const int tid = threadIdx.x;

    int m = 0;
    for (int i = tid; i < NK; i += PREP_T) m = max(m, base[i]);
#pragma unroll
    for (int o = 16; o > 0; o >>= 1) m = max(m, __shfl_xor_sync(0xffffffffu, m, o));
    if ((tid & 31) == 0) spart[tid >> 5] = m;
    __syncthreads();
    if (tid == 0) {
        int mm = 0;
        for (int w = 0; w < PREP_T / 32; w++) mm = max(mm, spart[w]);
        g_padmax = mm;
    }

    for (int i = tid; i < PBINS; i += PREP_T) sbins[i] = 0;
    __syncthreads();

    for (int i = tid; i < NK; i += PREP_T)
        atomicAdd(&sbins[sort_key(dil[i], lo[i])], 1);
    __syncthreads();

    int s = 0;
#pragma unroll
    for (int j = 0; j < 6; j++) s += sbins[tid * 6 + j];
    spart[tid] = s;
    __syncthreads();
    for (int off = 1; off < PREP_T; off <<= 1) {
        int v = spart[tid];
        int u = (tid >= off) ? spart[tid - off] : 0;
        __syncthreads();
        spart[tid] = v + u;
        __syncthreads();
    }
    int run = (tid > 0) ? spart[tid - 1] : 0;
#pragma unroll
    for (int j = 0; j < 6; j++) {
        int c = sbins[tid * 6 + j];
        sbins[tid * 6 + j] = run;
        run += c;
    }
    __syncthreads();

    for (int i = tid; i < NK; i += PREP_T) {
        int pos = atomicAdd(&sbins[sort_key(dil[i], lo[i])], 1);
        g_perm[pos] = i;
    }
}

// ---- dual-ring conv body: two independent streams (A, B) over strided
// subsequences, each a ring of 11 float2 samples (2 batches interleaved).
// One trip = 2 LDS.64 + 44 FMA. nqA >= nqB required (B may be 0).
__device__ __forceinline__ void dual_ring(
    const float2* pA, const float2* pB, int nqA, int nqB, int d,
    const float w[KSMAX], float bias,
    float& max0, float& max1, int& cnt0, int& cnt1)
{
    float2 yA[KSMAX], yB[KSMAX];
#pragma unroll
    for (int j = 0; j < 10; j++) { yA[j] = pA[j * d]; yB[j] = pB[j * d]; }
    const float2* ptrA = pA + 10 * d;
    const float2* ptrB = pB + 10 * d;

    const int nch = (nqA + 10) / 11;
    for (int c = 0, qb = 0; c < nch; c++, qb += 11) {
#pragma unroll
        for (int u = 0; u < KSMAX; u++) {
            const float2 nA = *ptrA; ptrA += d;
            const float2 nB = *ptrB; ptrB += d;
            yA[(10 + u) % KSMAX] = nA;
            yB[(10 + u) % KSMAX] = nB;
            float aA0 = bias, aA1 = bias, aB0 = bias, aB1 = bias;
#pragma unroll
            for (int j = 0; j < KSMAX; j++) {
                const float2 ya = yA[(u + j) % KSMAX];
                const float2 yb = yB[(u + j) % KSMAX];
                aA0 = fmaf(w[j], ya.x, aA0);
                aA1 = fmaf(w[j], ya.y, aA1);
                aB0 = fmaf(w[j], yb.x, aB0);
                aB1 = fmaf(w[j], yb.y, aB1);
            }
            const bool vA = (qb + u) < nqA;
            const bool vB = (qb + u) < nqB;
            max0 = (vA && aA0 > max0) ? aA0 : max0;
            max1 = (vA && aA1 > max1) ? aA1 : max1;
            cnt0 += (vA && aA0 > 0.0f) ? 1 : 0;
            cnt1 += (vA && aA1 > 0.0f) ? 1 : 0;
            max0 = (vB && aB0 > max0) ? aB0 : max0;
            max1 = (vB && aB1 > max1) ? aB1 : max1;
            cnt0 += (vB && aB0 > 0.0f) ? 1 : 0;
            cnt1 += (vB && aB1 > 0.0f) ? 1 : 0;
        }
    }
}

// ---- main kernel: one thread = (batch-pair, kernel), phases paired ----
__global__ __launch_bounds__(TPB) void rocket_main_kernel(
    const float* __restrict__ x,
    const float* __restrict__ W,
    const float* __restrict__ Bias,
    const int*   __restrict__ base,
    const int*   __restrict__ dil,
    const int*   __restrict__ lo,
    float*       __restrict__ out)
{
    __shared__ float2 sh[SH_LEN];   // 32KB
    const int b0  = 2 * blockIdx.y;
    const int tid = threadIdx.x;
    const int padmax = g_padmax;

    for (int i = tid; i < SH_LEN; i += TPB) sh[i] = make_float2(0.0f, 0.0f);
    __syncthreads();
    for (int i = tid; i < SEQ; i += TPB)
        sh[padmax + i] = make_float2(x[b0 * SEQ + i], x[(b0 + 1) * SEQ + i]);
    __syncthreads();

    const int idx = blockIdx.x * TPB + tid;
    if (idx >= NK) return;
    const int k = g_perm[NK - 1 - idx];      // reversed: largest-d first

    float w[KSMAX];
#pragma unroll
    for (int j = 0; j < KSMAX; j++) w[j] = W[k * KSMAX + j];
    const float bias = Bias[k];
    const int bs = base[k];
    const int d  = dil[k];
    const int L  = lo[k];

    float max0 = -INFINITY, max1 = -INFINITY;
    int   cnt0 = 0, cnt1 = 0;

    if (d >= 2) {
        const int q0  = (L - 1) / d;
        const int rem = (L - 1) - q0 * d;
        const int rmax = min(d, L);
        for (int r = 0; r < rmax; r += 2) {
            const int nqA = (r <= rem) ? (q0 + 1) : q0;
            const bool hasB = (r + 1) < rmax;
            const int nqB = hasB ? (((r + 1) <= rem) ? (q0 + 1) : q0) : 0;
            const float2* pA = sh + bs + r;
            dual_ring(pA, pA + 1, nqA, nqB, d, w, bias, max0, max1, cnt0, cnt1);
        }
    } else {
        const int nA = (L + 1) >> 1;
        const int nB = L - nA;
        const float2* pA = sh + bs;
        dual_ring(pA, pA + nA, nA, nB, 1, w, bias, max0, max1, cnt0, cnt1);
    }

    const float invL = 1.0f / (float)L;
    float2* o0 = (float2*)(out + (size_t)b0 * (2 * NK) + 2 * k);
    float2* o1 = (float2*)(out + (size_t)(b0 + 1) * (2 * NK) + 2 * k);
    *o0 = make_float2(max0, (float)cnt0 * invL);
    *o1 = make_float2(max1, (float)cnt1 * invL);
}

extern "C" void kernel_launch(void* const* d_in, const int* in_sizes, int n_in,
                              void* d_out, int out_size) {
    const float* x    = (const float*)d_in[0];
    const float* Wt   = (const float*)d_in[1];
    const float* Bias = (const float*)d_in[2];
    const int*   base = (const int*)d_in[3];
    const int*   dil  = (const int*)d_in[4];
    const int*   lo   = (const int*)d_in[5];
    float* out = (float*)d_out;

    prep_fused_kernel<<<1, PREP_T>>>(base, dil, lo);

    const int nblk = (NK + TPB - 1) / TPB;
    dim3 grid(nblk, 4);
    rocket_main_kernel<<<grid, TPB>>>(x, Wt, Bias, base, dil, lo, out);
}

// round 5
// speedup vs baseline: 1.2393x; 1.0623x over previous
#include <cuda_runtime.h>
#include <math.h>

#define NK      10000
#define SEQ     512
#define KSMAX   11
#define SH_LEN  4096     // max (padded) read index ~3400 < 4096
#define TPB     128
#define PREP_T  1024
#define PBINS   6144     // key = clamp(d,0,95)*64 + min(L>>4,63)

__device__ int g_padmax;
__device__ int g_perm[NK];

__device__ __forceinline__ int sort_key(int d, int L) {
    if (d < 0) d = 0;
    if (d > 95) d = 95;
    int lb = L >> 4;
    if (lb < 0) lb = 0;
    if (lb > 63) lb = 63;
    return d * 64 + lb;
}

// ---- single fused prep kernel: padmax + counting sort by (dil, lo-bucket) ----
__global__ __launch_bounds__(PREP_T) void prep_fused_kernel(
    const int* __restrict__ base,
    const int* __restrict__ dil,
    const int* __restrict__ lo)
{
    __shared__ int sbins[PBINS];
    __shared__ int spart[PREP_T];
    const int tid = threadIdx.x;

    int m = 0;
    for (int i = tid; i < NK; i += PREP_T) m = max(m, base[i]);
#pragma unroll
    for (int o = 16; o > 0; o >>= 1) m = max(m, __shfl_xor_sync(0xffffffffu, m, o));
    if ((tid & 31) == 0) spart[tid >> 5] = m;
    __syncthreads();
    if (tid == 0) {
        int mm = 0;
        for (int w = 0; w < PREP_T / 32; w++) mm = max(mm, spart[w]);
        g_padmax = mm;
    }

    for (int i = tid; i < PBINS; i += PREP_T) sbins[i] = 0;
    __syncthreads();

    for (int i = tid; i < NK; i += PREP_T)
        atomicAdd(&sbins[sort_key(dil[i], lo[i])], 1);
    __syncthreads();

    int s = 0;
#pragma unroll
    for (int j = 0; j < 6; j++) s += sbins[tid * 6 + j];
    spart[tid] = s;
    __syncthreads();
    for (int off = 1; off < PREP_T; off <<= 1) {
        int v = spart[tid];
        int u = (tid >= off) ? spart[tid - off] : 0;
        __syncthreads();
        spart[tid] = v + u;
        __syncthreads();
    }
    int run = (tid > 0) ? spart[tid - 1] : 0;
#pragma unroll
    for (int j = 0; j < 6; j++) {
        int c = sbins[tid * 6 + j];
        sbins[tid * 6 + j] = run;
        run += c;
    }
    __syncthreads();

    for (int i = tid; i < NK; i += PREP_T) {
        int pos = atomicAdd(&sbins[sort_key(dil[i], lo[i])], 1);
        g_perm[pos] = i;
    }
}

// ---- dual-ring conv body: two independent streams (A, B), each a ring of 11
// float2 samples (2 batches interleaved). One trip = 2 LDS.64 + 44 FMA.
// Requires nqA >= nqB (B may be 0).
__device__ __forceinline__ void dual_ring(
    const float2* pA, const float2* pB, int nqA, int nqB, int d,
    const float w[KSMAX], float bias,
    float& max0, float& max1, int& cnt0, int& cnt1)
{
    float2 yA[KSMAX], yB[KSMAX];
#pragma unroll
    for (int j = 0; j < 10; j++) { yA[j] = pA[j * d]; yB[j] = pB[j * d]; }
    const float2* ptrA = pA + 10 * d;
    const float2* ptrB = pB + 10 * d;

    const int nch = (nqA + 10) / 11;
    for (int c = 0, qb = 0; c < nch; c++, qb += 11) {
#pragma unroll
        for (int u = 0; u < KSMAX; u++) {
            const float2 nA = *ptrA; ptrA += d;
            const float2 nB = *ptrB; ptrB += d;
            yA[(10 + u) % KSMAX] = nA;
            yB[(10 + u) % KSMAX] = nB;
            float aA0 = bias, aA1 = bias, aB0 = bias, aB1 = bias;
#pragma unroll
            for (int j = 0; j < KSMAX; j++) {
                const float2 ya = yA[(u + j) % KSMAX];
                const float2 yb = yB[(u + j) % KSMAX];
                aA0 = fmaf(w[j], ya.x, aA0);
                aA1 = fmaf(w[j], ya.y, aA1);
                aB0 = fmaf(w[j], yb.x, aB0);
                aB1 = fmaf(w[j], yb.y, aB1);
            }
            const bool vA = (qb + u) < nqA;
            const bool vB = (qb + u) < nqB;
            max0 = (vA && aA0 > max0) ? aA0 : max0;
            max1 = (vA && aA1 > max1) ? aA1 : max1;
            cnt0 += (vA && aA0 > 0.0f) ? 1 : 0;
            cnt1 += (vA && aA1 > 0.0f) ? 1 : 0;
            max0 = (vB && aB0 > max0) ? aB0 : max0;
            max1 = (vB && aB1 > max1) ? aB1 : max1;
            cnt0 += (vB && aB0 > 0.0f) ? 1 : 0;
            cnt1 += (vB && aB1 > 0.0f) ? 1 : 0;
        }
    }
}

// ---- main kernel: TWO threads (adjacent lanes) per (batch-pair, kernel).
// Lane s handles phases r === s (mod 2); shuffle-combine at the end.
__global__ __launch_bounds__(TPB) void rocket_main_kernel(
    const float* __restrict__ x,
    const float* __restrict__ W,
    const float* __restrict__ Bias,
    const int*   __restrict__ base,
    const int*   __restrict__ dil,
    const int*   __restrict__ lo,
    float*       __restrict__ out)
{
    __shared__ float2 sh[SH_LEN];   // 32KB
    const int b0  = 2 * blockIdx.y;
    const int tid = threadIdx.x;
    const int padmax = g_padmax;

    for (int i = tid; i < SH_LEN; i += TPB) sh[i] = make_float2(0.0f, 0.0f);
    __syncthreads();
    for (int i = tid; i < SEQ; i += TPB)
        sh[padmax + i] = make_float2(x[b0 * SEQ + i], x[(b0 + 1) * SEQ + i]);
    __syncthreads();

    const int idx = blockIdx.x * TPB + tid;
    const bool live = idx < 2 * NK;
    int slot = idx >> 1;
    if (slot > NK - 1) slot = NK - 1;         // clamp; keep lanes alive for shuffle
    const int s = idx & 1;
    const int k = g_perm[NK - 1 - slot];      // reversed: largest-d first

    float w[KSMAX];
#pragma unroll
    for (int j = 0; j < KSMAX; j++) w[j] = W[k * KSMAX + j];
    const float bias = Bias[k];
    const int bs = base[k];
    const int d  = dil[k];
    const int L  = lo[k];

    float max0 = -INFINITY, max1 = -INFINITY;
    int   cnt0 = 0, cnt1 = 0;

    if (d >= 2) {
        const int q0  = (L - 1) / d;
        const int rem = (L - 1) - q0 * d;
        const int rmax = min(d, L);
        // lane s: phases r and r+2 per trip, r = s, s+4, s+8, ...
        for (int r = s; r < rmax; r += 4) {
            const int nqA = (r <= rem) ? (q0 + 1) : q0;
            const int r2 = r + 2;
            const int nqB = (r2 < rmax) ? ((r2 <= rem) ? (q0 + 1) : q0) : 0;
            const float2* pA = sh + bs + r;
            dual_ring(pA, pA + 2, nqA, nqB, d, w, bias, max0, max1, cnt0, cnt1);
        }
    } else {
        // single phase: split q-range into 4 chunks; lane s takes chunks 2s, 2s+1
        const int c = (L + 3) >> 2;
        const int o0 = 2 * s * c;
        const int o1 = o0 + c;
        int nA = min(c, max(L - o0, 0));
        int nB = min(c, max(L - o1, 0));
        if (nA > 0) {
            dual_ring(sh + bs + o0, sh + bs + o1, nA, nB, 1, w, bias,
                      max0, max1, cnt0, cnt1);
        }
    }

    // combine lane pair (s=0 with s=1)
    const unsigned mask = 0xffffffffu;
    max0 = fmaxf(max0, __shfl_xor_sync(mask, max0, 1));
    max1 = fmaxf(max1, __shfl_xor_sync(mask, max1, 1));
    cnt0 += __shfl_xor_sync(mask, cnt0, 1);
    cnt1 += __shfl_xor_sync(mask, cnt1, 1);

    if (live && s == 0) {
        const float invL = 1.0f / (float)L;
        float2* o0p = (float2*)(out + (size_t)b0 * (2 * NK) + 2 * k);
        float2* o1p = (float2*)(out + (size_t)(b0 + 1) * (2 * NK) + 2 * k);
        *o0p = make_float2(max0, (float)cnt0 * invL);
        *o1p = make_float2(max1, (float)cnt1 * invL);
    }
}

extern "C" void kernel_launch(void* const* d_in, const int* in_sizes, int n_in,
                              void* d_out, int out_size) {
    const float* x    = (const float*)d_in[0];
    const float* Wt   = (const float*)d_in[1];
    const float* Bias = (const float*)d_in[2];
    const int*   base = (const int*)d_in[3];
    const int*   dil  = (const int*)d_in[4];
    const int*   lo   = (const int*)d_in[5];
    float* out = (float*)d_out;

    prep_fused_kernel<<<1, PREP_T>>>(base, dil, lo);

    const int nblk = (2 * NK + TPB - 1) / TPB;   // 157
    dim3 grid(nblk, 4);
    rocket_main_kernel<<<grid, TPB>>>(x, Wt, Bias, base, dil, lo, out);
}

// round 6
// speedup vs baseline: 1.3674x; 1.1034x over previous
#include <cuda_runtime.h>
#include <math.h>

#define NK      10000
#define SEQ     512
#define KSMAX   11
#define SH_LEN  4096     // max (padded) read index ~3400 < 4096
#define TPB     128
#define PREP_T  1024
#define PBINS   6144     // key = clamp(d,0,95)*64 + min(L>>4,63)

__device__ int g_padmax;
__device__ int g_perm[NK];

__device__ __forceinline__ int sort_key(int d, int L) {
    if (d < 0) d = 0;
    if (d > 95) d = 95;
    int lb = L >> 4;
    if (lb < 0) lb = 0;
    if (lb > 63) lb = 63;
    return d * 64 + lb;
}

// ---- single fused prep kernel: padmax + counting sort by (dil, lo-bucket) ----
__global__ __launch_bounds__(PREP_T) void prep_fused_kernel(
    const int* __restrict__ base,
    const int* __restrict__ dil,
    const int* __restrict__ lo)
{
    __shared__ int sbins[PBINS];
    __shared__ int spart[PREP_T];
    const int tid = threadIdx.x;

    int m = 0;
    for (int i = tid; i < NK; i += PREP_T) m = max(m, base[i]);
#pragma unroll
    for (int o = 16; o > 0; o >>= 1) m = max(m, __shfl_xor_sync(0xffffffffu, m, o));
    if ((tid & 31) == 0) spart[tid >> 5] = m;
    __syncthreads();
    if (tid == 0) {
        int mm = 0;
        for (int w = 0; w < PREP_T / 32; w++) mm = max(mm, spart[w]);
        g_padmax = mm;
    }

    for (int i = tid; i < PBINS; i += PREP_T) sbins[i] = 0;
    __syncthreads();

    for (int i = tid; i < NK; i += PREP_T)
        atomicAdd(&sbins[sort_key(dil[i], lo[i])], 1);
    __syncthreads();

    int s = 0;
#pragma unroll
    for (int j = 0; j < 6; j++) s += sbins[tid * 6 + j];
    spart[tid] = s;
    __syncthreads();
    for (int off = 1; off < PREP_T; off <<= 1) {
        int v = spart[tid];
        int u = (tid >= off) ? spart[tid - off] : 0;
        __syncthreads();
        spart[tid] = v + u;
        __syncthreads();
    }
    int run = (tid > 0) ? spart[tid - 1] : 0;
#pragma unroll
    for (int j = 0; j < 6; j++) {
        int c = sbins[tid * 6 + j];
        sbins[tid * 6 + j] = run;
        run += c;
    }
    __syncthreads();

    for (int i = tid; i < NK; i += PREP_T) {
        int pos = atomicAdd(&sbins[sort_key(dil[i], lo[i])], 1);
        g_perm[pos] = i;
    }
}

// ---- single-ring body: one strided stream, ring of 11 float2 samples.
// Full chunks unconditional; tail chunks predicated.
__device__ __forceinline__ void single_ring(
    const float2* p, int nq, int d,
    const float w[KSMAX], float bias,
    float& max0, float& max1, int& cnt0, int& cnt1)
{
    float2 y[KSMAX];
#pragma unroll
    for (int j = 0; j < 10; j++) y[j] = p[j * d];
    const float2* ptr = p + 10 * d;

    int qb = 0;
    for (; qb + KSMAX <= nq; qb += KSMAX) {
#pragma unroll
        for (int u = 0; u < KSMAX; u++) {
            const float2 nA = *ptr; ptr += d;
            y[(10 + u) % KSMAX] = nA;
            float a0 = bias, a1 = bias;
#pragma unroll
            for (int j = 0; j < KSMAX; j++) {
                const float2 yy = y[(u + j) % KSMAX];
                a0 = fmaf(w[j], yy.x, a0);
                a1 = fmaf(w[j], yy.y, a1);
            }
            max0 = fmaxf(max0, a0);
            max1 = fmaxf(max1, a1);
            cnt0 += (a0 > 0.0f) ? 1 : 0;
            cnt1 += (a1 > 0.0f) ? 1 : 0;
        }
    }
    for (; qb < nq; qb += KSMAX) {
#pragma unroll
        for (int u = 0; u < KSMAX; u++) {
            const float2 nA = *ptr; ptr += d;
            y[(10 + u) % KSMAX] = nA;
            float a0 = bias, a1 = bias;
#pragma unroll
            for (int j = 0; j < KSMAX; j++) {
                const float2 yy = y[(u + j) % KSMAX];
                a0 = fmaf(w[j], yy.x, a0);
                a1 = fmaf(w[j], yy.y, a1);
            }
            const bool v = (qb + u) < nq;
            max0 = (v && a0 > max0) ? a0 : max0;
            max1 = (v && a1 > max1) ? a1 : max1;
            cnt0 += (v && a0 > 0.0f) ? 1 : 0;
            cnt1 += (v && a1 > 0.0f) ? 1 : 0;
        }
    }
}

// ---- dual-ring body: two independent streams; full-both chunks
// unconditional, remainder predicated. Requires nqA >= nqB >= 1.
__device__ __forceinline__ void dual_ring(
    const float2* pA, const float2* pB, int nqA, int nqB, int d,
    const float w[KSMAX], float bias,
    float& max0, float& max1, int& cnt0, int& cnt1)
{
    float2 yA[KSMAX], yB[KSMAX];
#pragma unroll
    for (int j = 0; j < 10; j++) { yA[j] = pA[j * d]; yB[j] = pB[j * d]; }
    const float2* ptrA = pA + 10 * d;
    const float2* ptrB = pB + 10 * d;

    int qb = 0;
    for (; qb + KSMAX <= nqB; qb += KSMAX) {        // valid for BOTH streams
#pragma unroll
        for (int u = 0; u < KSMAX; u++) {
            const float2 nA = *ptrA; ptrA += d;
            const float2 nB = *ptrB; ptrB += d;
            yA[(10 + u) % KSMAX] = nA;
            yB[(10 + u) % KSMAX] = nB;
            float aA0 = bias, aA1 = bias, aB0 = bias, aB1 = bias;
#pragma unroll
            for (int j = 0; j < KSMAX; j++) {
                const float2 ya = yA[(u + j) % KSMAX];
                const float2 yb = yB[(u + j) % KSMAX];
                aA0 = fmaf(w[j], ya.x, aA0);
                aA1 = fmaf(w[j], ya.y, aA1);
                aB0 = fmaf(w[j], yb.x, aB0);
                aB1 = fmaf(w[j], yb.y, aB1);
            }
            max0 = fmaxf(fmaxf(max0, aA0), aB0);
            max1 = fmaxf(fmaxf(max1, aA1), aB1);
            cnt0 += ((aA0 > 0.0f) ? 1 : 0) + ((aB0 > 0.0f) ? 1 : 0);
            cnt1 += ((aA1 > 0.0f) ? 1 : 0) + ((aB1 > 0.0f) ? 1 : 0);
        }
    }
    for (; qb < nqA; qb += KSMAX) {                 // predicated remainder
#pragma unroll
        for (int u = 0; u < KSMAX; u++) {
            const float2 nA = *ptrA; ptrA += d;
            const float2 nB = *ptrB; ptrB += d;
            yA[(10 + u) % KSMAX] = nA;
            yB[(10 + u) % KSMAX] = nB;
            float aA0 = bias, aA1 = bias, aB0 = bias, aB1 = bias;
#pragma unroll
            for (int j = 0; j < KSMAX; j++) {
                const float2 ya = yA[(u + j) % KSMAX];
                const float2 yb = yB[(u + j) % KSMAX];
                aA0 = fmaf(w[j], ya.x, aA0);
                aA1 = fmaf(w[j], ya.y, aA1);
                aB0 = fmaf(w[j], yb.x, aB0);
                aB1 = fmaf(w[j], yb.y, aB1);
            }
            const bool vA = (qb + u) < nqA;
            const bool vB = (qb + u) < nqB;
            max0 = (vA && aA0 > max0) ? aA0 : max0;
            max1 = (vA && aA1 > max1) ? aA1 : max1;
            cnt0 += (vA && aA0 > 0.0f) ? 1 : 0;
            cnt1 += (vA && aA1 > 0.0f) ? 1 : 0;
            max0 = (vB && aB0 > max0) ? aB0 : max0;
            max1 = (vB && aB1 > max1) ? aB1 : max1;
            cnt0 += (vB && aB0 > 0.0f) ? 1 : 0;
            cnt1 += (vB && aB1 > 0.0f) ? 1 : 0;
        }
    }
}

// ---- main kernel: FOUR threads (adjacent lanes) per (batch-pair, kernel) ----
__global__ __launch_bounds__(TPB) void rocket_main_kernel(
    const float* __restrict__ x,
    const float* __restrict__ W,
    const float* __restrict__ Bias,
    const int*   __restrict__ base,
    const int*   __restrict__ dil,
    const int*   __restrict__ lo,
    float*       __restrict__ out)
{
    __shared__ float2 sh[SH_LEN];   // 32KB
    const int b0  = 2 * blockIdx.y;
    const int tid = threadIdx.x;
    const int padmax = g_padmax;

    for (int i = tid; i < SH_LEN; i += TPB) sh[i] = make_float2(0.0f, 0.0f);
    __syncthreads();
    for (int i = tid; i < SEQ; i += TPB)
        sh[padmax + i] = make_float2(x[b0 * SEQ + i], x[(b0 + 1) * SEQ + i]);
    __syncthreads();

    const int idx = blockIdx.x * TPB + tid;
    const bool live = idx < 4 * NK;
    int slot = idx >> 2;
    if (slot > NK - 1) slot = NK - 1;       // clamp; keep lanes alive for shuffles
    const int s = idx & 3;
    const int k = g_perm[NK - 1 - slot];    // reversed: largest-d first

    float w[KSMAX];
#pragma unroll
    for (int j = 0; j < KSMAX; j++) w[j] = W[k * KSMAX + j];
    const float bias = Bias[k];
    const int bs = base[k];
    const int d  = dil[k];
    const int L  = lo[k];

    float max0 = -INFINITY, max1 = -INFINITY;
    int   cnt0 = 0, cnt1 = 0;

    if (d >= 4) {
        const int q0  = (L - 1) / d;
        const int rem = (L - 1) - q0 * d;
        const int rmax = min(d, L);
        for (int r = s; r < rmax; r += 8) {
            const int nqA = (r <= rem) ? (q0 + 1) : q0;
            const int r2 = r + 4;
            const int nqB = (r2 < rmax) ? ((r2 <= rem) ? (q0 + 1) : q0) : 0;
            const float2* pA = sh + bs + r;
            if (nqB > 0)
                dual_ring(pA, sh + bs + r2, nqA, nqB, d, w, bias,
                          max0, max1, cnt0, cnt1);
            else
                single_ring(pA, nqA, d, w, bias, max0, max1, cnt0, cnt1);
        }
    } else if (d == 3) {
        if (s < 3) {
            const int q0  = (L - 1) / 3;
            const int rem = (L - 1) - 3 * q0;
            const int nq  = (s <= rem) ? (q0 + 1) : q0;
            const int nA  = (nq + 1) >> 1;
            const int nB  = nq - nA;
            const float2* pA = sh + bs + s;
            if (nB > 0)
                dual_ring(pA, pA + nA * 3, nA, nB, 3, w, bias,
                          max0, max1, cnt0, cnt1);
            else if (nA > 0)
                single_ring(pA, nA, 3, w, bias, max0, max1, cnt0, cnt1);
        }
    } else if (d == 2) {
        const int q0  = (L - 1) >> 1;
        const int rem = (L - 1) & 1;
        const int nq0 = q0 + 1;
        const int nq1 = (rem >= 1) ? (q0 + 1) : q0;
        const int c   = (nq0 + 3) >> 2;
        const int st  = s * c;
        const int nA  = min(c, max(nq0 - st, 0));
        const int nB  = min(c, max(nq1 - st, 0));
        const float2* pA = sh + bs + 2 * st;        // phase 0
        const float2* pB = sh + bs + 1 + 2 * st;    // phase 1
        if (nB > 0)
            dual_ring(pA, pB, nA, nB, 2, w, bias, max0, max1, cnt0, cnt1);
        else if (nA > 0)
            single_ring(pA, nA, 2, w, bias, max0, max1, cnt0, cnt1);
    } else { // d == 1
        const int c  = (L + 7) >> 3;
        const int st = 2 * s * c;
        const int nA = min(c, max(L - st, 0));
        const int nB = min(c, max(L - st - c, 0));
        const float2* pA = sh + bs + st;
        if (nB > 0)
            dual_ring(pA, pA + c, nA, nB, 1, w, bias, max0, max1, cnt0, cnt1);
        else if (nA > 0)
            single_ring(pA, nA, 1, w, bias, max0, max1, cnt0, cnt1);
    }

    // combine group of 4 lanes
    const unsigned mask = 0xffffffffu;
#pragma unroll
    for (int o = 1; o <= 2; o <<= 1) {
        max0 = fmaxf(max0, __shfl_xor_sync(mask, max0, o));
        max1 = fmaxf(max1, __shfl_xor_sync(mask, max1, o));
        cnt0 += __shfl_xor_sync(mask, cnt0, o);
        cnt1 += __shfl_xor_sync(mask, cnt1, o);
    }

    if (live && s == 0) {
        const float invL = 1.0f / (float)L;
        float2* o0p = (float2*)(out + (size_t)b0 * (2 * NK) + 2 * k);
        float2* o1p = (float2*)(out + (size_t)(b0 + 1) * (2 * NK) + 2 * k);
        *o0p = make_float2(max0, (float)cnt0 * invL);
        *o1p = make_float2(max1, (float)cnt1 * invL);
    }
}

extern "C" void kernel_launch(void* const* d_in, const int* in_sizes, int n_in,
                              void* d_out, int out_size) {
    const float* x    = (const float*)d_in[0];
    const float* Wt   = (const float*)d_in[1];
    const float* Bias = (const float*)d_in[2];
    const int*   base = (const int*)d_in[3];
    const int*   dil  = (const int*)d_in[4];
    const int*   lo   = (const int*)d_in[5];
    float* out = (float*)d_out;

    prep_fused_kernel<<<1, PREP_T>>>(base, dil, lo);

    const int nblk = (4 * NK + TPB - 1) / TPB;   // 313
    dim3 grid(nblk, 4);
    rocket_main_kernel<<<grid, TPB>>>(x, Wt, Bias, base, dil, lo, out);
}

// round 7
// speedup vs baseline: 1.7351x; 1.2689x over previous
#include <cuda_runtime.h>
#include <math.h>

#define NK      10000
#define SEQ     512
#define KSMAX   11
#define SH_LEN  2048     // max read index proven <= ~1881
#define TPB     128
#define GL      8        // lanes per (batch-pair, kernel)
#define PREP_T  1024
#define PBINS   6144     // key = clamp(d,0,95)*64 + min(L>>4,63)

__device__ int g_padmax;
__device__ int g_perm[NK];

__device__ __forceinline__ int sort_key(int d, int L) {
    if (d < 0) d = 0;
    if (d > 95) d = 95;
    int lb = L >> 4;
    if (lb < 0) lb = 0;
    if (lb > 63) lb = 63;
    return d * 64 + lb;
}

// ---- single fused prep kernel: padmax + counting sort by (dil, lo-bucket) ----
__global__ __launch_bounds__(PREP_T) void prep_fused_kernel(
    const int* __restrict__ base,
    const int* __restrict__ dil,
    const int* __restrict__ lo)
{
    __shared__ int sbins[PBINS];
    __shared__ int spart[PREP_T];
    const int tid = threadIdx.x;

    int m = 0;
    for (int i = tid; i < NK; i += PREP_T) m = max(m, base[i]);
#pragma unroll
    for (int o = 16; o > 0; o >>= 1) m = max(m, __shfl_xor_sync(0xffffffffu, m, o));
    if ((tid & 31) == 0) spart[tid >> 5] = m;
    __syncthreads();
    if (tid == 0) {
        int mm = 0;
        for (int w = 0; w < PREP_T / 32; w++) mm = max(mm, spart[w]);
        g_padmax = mm;
    }

    for (int i = tid; i < PBINS; i += PREP_T) sbins[i] = 0;
    __syncthreads();

    for (int i = tid; i < NK; i += PREP_T)
        atomicAdd(&sbins[sort_key(dil[i], lo[i])], 1);
    __syncthreads();

    int s = 0;
#pragma unroll
    for (int j = 0; j < 6; j++) s += sbins[tid * 6 + j];
    spart[tid] = s;
    __syncthreads();
    for (int off = 1; off < PREP_T; off <<= 1) {
        int v = spart[tid];
        int u = (tid >= off) ? spart[tid - off] : 0;
        __syncthreads();
        spart[tid] = v + u;
        __syncthreads();
    }
    int run = (tid > 0) ? spart[tid - 1] : 0;
#pragma unroll
    for (int j = 0; j < 6; j++) {
        int c = sbins[tid * 6 + j];
        sbins[tid * 6 + j] = run;
        run += c;
    }
    __syncthreads();

    for (int i = tid; i < NK; i += PREP_T) {
        int pos = atomicAdd(&sbins[sort_key(dil[i], lo[i])], 1);
        g_perm[pos] = i;
    }
}

// one ring trip at static rotation u: 1 LDS.64 + 22 FMA + 2 FMNMX + 2 cnt
#define RING_TRIP(u)                                                        \
    do {                                                                    \
        const float2 nv = *ptr; ptr += d;                                   \
        y[(10 + (u)) % KSMAX] = nv;                                         \
        float a0 = bias, a1 = bias;                                         \
        _Pragma("unroll")                                                   \
        for (int j = 0; j < KSMAX; j++) {                                   \
            const float2 yy = y[((u) + j) % KSMAX];                         \
            a0 = fmaf(w[j], yy.x, a0);                                      \
            a1 = fmaf(w[j], yy.y, a1);                                      \
        }                                                                   \
        max0 = fmaxf(max0, a0);                                             \
        max1 = fmaxf(max1, a1);                                             \
        cnt0 += (a0 > 0.0f) ? 1 : 0;                                        \
        cnt1 += (a1 > 0.0f) ? 1 : 0;                                        \
    } while (0)

// ring over one strided stream: full 11-chunks unconditional, tail via
// uniform branch-exit. No predicated garbage trips, no per-trip ISETP.
__device__ __forceinline__ void ring_run(
    const float2* __restrict__ p, int n, int d,
    const float w[KSMAX], float bias,
    float& max0, float& max1, int& cnt0, int& cnt1)
{
    float2 y[KSMAX];
#pragma unroll
    for (int j = 0; j < 10; j++) y[j] = p[j * d];
    const float2* ptr = p + 10 * d;

    while (n >= KSMAX) {
#pragma unroll
        for (int u = 0; u < KSMAX; u++) RING_TRIP(u);
        n -= KSMAX;
    }
#pragma unroll
    for (int u = 0; u < KSMAX - 1; u++) {
        if (u >= n) break;      // uniform within warp (sorted work)
        RING_TRIP(u);
    }
}

// ---- main kernel: 8 lanes per (batch-pair, kernel); lane s owns outputs
// [s*L/8, (s+1)*L/8) in flattened (phase, q) order -> exact balance.
__global__ __launch_bounds__(TPB) void rocket_main_kernel(
    const float* __restrict__ x,
    const float* __restrict__ W,
    const float* __restrict__ Bias,
    const int*   __restrict__ base,
    const int*   __restrict__ dil,
    const int*   __restrict__ lo,
    float*       __restrict__ out)
{
    __shared__ float2 sh[SH_LEN];   // 16KB
    const int b0  = 2 * blockIdx.y;
    const int tid = threadIdx.x;
    const int padmax = g_padmax;

    for (int i = tid; i < SH_LEN; i += TPB) sh[i] = make_float2(0.0f, 0.0f);
    __syncthreads();
    for (int i = tid; i < SEQ; i += TPB)
        sh[padmax + i] = make_float2(x[b0 * SEQ + i], x[(b0 + 1) * SEQ + i]);
    __syncthreads();

    const int idx  = blockIdx.x * TPB + tid;     // 0 .. 8*NK-1 exactly
    const int slot = idx >> 3;
    const int s    = idx & 7;
    const int k    = g_perm[NK - 1 - slot];      // largest-d first

    float w[KSMAX];
#pragma unroll
    for (int j = 0; j < KSMAX; j++) w[j] = W[k * KSMAX + j];
    const float bias = Bias[k];
    const int bs = base[k];
    const int d  = dil[k];
    const int L  = lo[k];

    // per-kernel phase geometry: nq(r) = q0+1 for r<=rem else q0
    const int q0  = (L - 1) / d;
    const int rem = (L - 1) - q0 * d;

    // lane output range [c_lo, c_hi) in flattened (phase,q) order
    const int c_lo = (s * L) >> 3;
    const int c_hi = ((s + 1) * L) >> 3;

    // locate start (r, q) such that cumulative-outputs-before == c_lo
    int r, q;
    {
        const int np  = q0 + 1;
        const int thr = (rem + 1) * np;
        if (c_lo < thr) { r = c_lo / np; q = c_lo - r * np; }
        else {
            const int c2 = c_lo - thr;
            const int rr = c2 / q0;
            r = rem + 1 + rr;
            q = c2 - rr * q0;
        }
    }

    float max0 = -INFINITY, max1 = -INFINITY;
    int   cnt0 = 0, cnt1 = 0;

    int left = c_hi - c_lo;
    while (left > 0) {
        const int nq_r = (r <= rem) ? (q0 + 1) : q0;
        const int n = min(nq_r - q, left);
        ring_run(sh + bs + r + q * d, n, d, w, bias, max0, max1, cnt0, cnt1);
        left -= n;
        ++r;
        q = 0;
    }

    // combine the 8-lane group
    const unsigned mask = 0xffffffffu;
#pragma unroll
    for (int o = 1; o <= 4; o <<= 1) {
        max0 = fmaxf(max0, __shfl_xor_sync(mask, max0, o));
        max1 = fmaxf(max1, __shfl_xor_sync(mask, max1, o));
        cnt0 += __shfl_xor_sync(mask, cnt0, o);
        cnt1 += __shfl_xor_sync(mask, cnt1, o);
    }

    if (s == 0) {
        const float invL = 1.0f / (float)L;
        float2* o0p = (float2*)(out + (size_t)b0 * (2 * NK) + 2 * k);
        float2* o1p = (float2*)(out + (size_t)(b0 + 1) * (2 * NK) + 2 * k);
        *o0p = make_float2(max0, (float)cnt0 * invL);
        *o1p = make_float2(max1, (float)cnt1 * invL);
    }
}

extern "C" void kernel_launch(void* const* d_in, const int* in_sizes, int n_in,
                              void* d_out, int out_size) {
    const float* x    = (const float*)d_in[0];
    const float* Wt   = (const float*)d_in[1];
    const float* Bias = (const float*)d_in[2];
    const int*   base = (const int*)d_in[3];
    const int*   dil  = (const int*)d_in[4];
    const int*   lo   = (const int*)d_in[5];
    float* out = (float*)d_out;

    prep_fused_kernel<<<1, PREP_T>>>(base, dil, lo);

    const int nblk = (GL * NK) / TPB;   // 625 exactly
    dim3 grid(nblk, 4);
    rocket_main_kernel<<<grid, TPB>>>(x, Wt, Bias, base, dil, lo, out);
}